// round 4
// baseline (speedup 1.0000x reference)
#include <cuda_runtime.h>
#include <cstdint>

// ---------------- problem constants ----------------
#define N_NODES 100000
#define IN_CH   512
#define HID_CH  256
#define OUT_CH  32
#define N_EDGES 1600000
#define K_STEPS 10
#define ALPHA   0.1f

// ---------------- device scratch (no allocations allowed) ----------------
__device__ float g_h0[(size_t)N_NODES * OUT_CH];   // h0 = relu(x@W1+b1)@W2+b2
__device__ float g_ha[(size_t)N_NODES * OUT_CH];   // ping
__device__ float g_hb[(size_t)N_NODES * OUT_CH];   // pong
__device__ float g_agg[(size_t)N_NODES * OUT_CH];  // per-step scatter accumulator
__device__ int   g_deg[N_NODES];
__device__ int   g_src[N_EDGES];
__device__ int   g_dst[N_EDGES];
__device__ float g_coef[N_EDGES];
__device__ int   g_idx64;                          // 1 if edge_index is int64

// ---------------- dtype detection ----------------
// If edge_index is int64, all high 32-bit words are 0 (indices in [0,1e5)).
// If int32, odd words are random indices -> essentially never all zero.
__global__ void detect_dtype_kernel(const int* __restrict__ ei32) {
    int t = threadIdx.x;
    int any = 0;
    for (int i = t; i < 1024; i += 32) any |= ei32[2 * i + 1];
#pragma unroll
    for (int o = 16; o; o >>= 1) any |= __shfl_xor_sync(0xffffffffu, any, o);
    if (t == 0) g_idx64 = (any == 0) ? 1 : 0;
}

__device__ __forceinline__ int load_idx(const void* ei, size_t pos, int is64) {
    long long v = is64 ? ((const long long*)ei)[pos] : (long long)((const int*)ei)[pos];
    if (v < 0) v = 0;
    if (v >= N_NODES) v = N_NODES - 1;
    return (int)v;
}

// ---------------- degree + edge precompute ----------------
__global__ void init_deg_kernel() {
    int i = blockIdx.x * blockDim.x + threadIdx.x;
    if (i < N_NODES) g_deg[i] = 1;  // self-loop
}

__global__ void deg_edges_kernel(const void* __restrict__ ei) {
    int e = blockIdx.x * blockDim.x + threadIdx.x;
    if (e >= N_EDGES) return;
    int is64 = g_idx64;
    atomicAdd(&g_deg[load_idx(ei, (size_t)N_EDGES + e, is64)], 1);
}

__global__ void precompute_edges_kernel(const void* __restrict__ ei) {
    int e = blockIdx.x * blockDim.x + threadIdx.x;
    if (e >= N_EDGES) return;
    int is64 = g_idx64;
    int s = load_idx(ei, e, is64);
    int d = load_idx(ei, (size_t)N_EDGES + e, is64);
    g_src[e]  = s;
    g_dst[e]  = d;
    g_coef[e] = rsqrtf((float)g_deg[s]) * rsqrtf((float)g_deg[d]);
}

__global__ void init_h0_bias_kernel(const float* __restrict__ b2) {
    int i = blockIdx.x * blockDim.x + threadIdx.x;
    if (i < N_NODES * OUT_CH) g_h0[i] = b2[i & 31];
}

__global__ void zero_agg_kernel() {
    int i = blockIdx.x * blockDim.x + threadIdx.x;
    if (i < N_NODES * OUT_CH) g_agg[i] = 0.0f;
}

// ---------------- fused MLP ----------------
// One block computes a 128-row x 64-hidden-channel tile of h1 = relu(x@W1+b1),
// then immediately multiplies it by W2[64-slice, 32] and atomically accumulates
// the 128x32 partial into g_h0 (which is preloaded with b2).
__global__ __launch_bounds__(256)
void mlp_fused_kernel(const float* __restrict__ x, const float* __restrict__ W1,
                      const float* __restrict__ b1, const float* __restrict__ W2) {
    union Smem {
        struct { float As[16][128]; float Bs[16][64]; } s1;   // 12 KB
        struct { float Cs[128][68]; float W2s[64][32]; } s2;  // 42 KB
    };
    __shared__ Smem u;

    const int tid  = threadIdx.x;
    const int brow = blockIdx.x * 128;
    const int bcol = blockIdx.y * 64;   // hidden-channel chunk
    const int tx = tid % 16;            // column group (4 cols each)
    const int ty = tid / 16;            // row group (8 rows each)

    float acc[8][4];
#pragma unroll
    for (int i = 0; i < 8; i++)
#pragma unroll
        for (int j = 0; j < 4; j++) acc[i][j] = 0.0f;

    // ---- stage 1: 128x64 tile of x@W1, K = 512 in steps of 16 ----
    for (int k0 = 0; k0 < IN_CH; k0 += 16) {
#pragma unroll
        for (int l = 0; l < 2; l++) {          // A: 128x16 = 512 float4
            int idx  = tid + l * 256;
            int row  = idx >> 2;
            int c4   = (idx & 3) * 4;
            int grow = brow + row;
            float4 v = make_float4(0.f, 0.f, 0.f, 0.f);
            if (grow < N_NODES)
                v = *(const float4*)&x[(size_t)grow * IN_CH + k0 + c4];
            u.s1.As[c4 + 0][row] = v.x;
            u.s1.As[c4 + 1][row] = v.y;
            u.s1.As[c4 + 2][row] = v.z;
            u.s1.As[c4 + 3][row] = v.w;
        }
        {                                      // B: 16x64 = 256 float4
            int row = tid >> 4;
            int c4  = (tid & 15) * 4;
            *(float4*)&u.s1.Bs[row][c4] =
                *(const float4*)&W1[(size_t)(k0 + row) * HID_CH + bcol + c4];
        }
        __syncthreads();

#pragma unroll
        for (int k = 0; k < 16; k++) {
            float a[8], b[4];
#pragma unroll
            for (int i = 0; i < 8; i++) a[i] = u.s1.As[k][ty * 8 + i];
#pragma unroll
            for (int j = 0; j < 4; j++) b[j] = u.s1.Bs[k][tx * 4 + j];
#pragma unroll
            for (int i = 0; i < 8; i++)
#pragma unroll
                for (int j = 0; j < 4; j++) acc[i][j] += a[i] * b[j];
        }
        __syncthreads();
    }

    // ---- relu(acc + b1) -> shared Cs ----
#pragma unroll
    for (int i = 0; i < 8; i++)
#pragma unroll
        for (int j = 0; j < 4; j++) {
            float v = acc[i][j] + b1[bcol + tx * 4 + j];
            u.s2.Cs[ty * 8 + i][tx * 4 + j] = fmaxf(v, 0.0f);
        }

    // ---- load W2 slice [64,32] ----
#pragma unroll
    for (int l = 0; l < 8; l++) {
        int q = tid + l * 256;
        u.s2.W2s[q >> 5][q & 31] = W2[(size_t)(bcol + (q >> 5)) * OUT_CH + (q & 31)];
    }
    __syncthreads();

    // ---- stage 2: Cs[128x64] @ W2s[64x32] -> atomic into g_h0 ----
    const int c  = tid & 31;   // output channel
    const int r0 = (tid >> 5) * 16;
    float sum[16];
#pragma unroll
    for (int rr = 0; rr < 16; rr++) sum[rr] = 0.0f;

#pragma unroll
    for (int k4 = 0; k4 < 16; k4++) {
        float w0 = u.s2.W2s[k4 * 4 + 0][c];
        float w1 = u.s2.W2s[k4 * 4 + 1][c];
        float w2 = u.s2.W2s[k4 * 4 + 2][c];
        float w3 = u.s2.W2s[k4 * 4 + 3][c];
#pragma unroll
        for (int rr = 0; rr < 16; rr++) {
            float4 cv = *(const float4*)&u.s2.Cs[r0 + rr][k4 * 4];
            sum[rr] += cv.x * w0 + cv.y * w1 + cv.z * w2 + cv.w * w3;
        }
    }
#pragma unroll
    for (int rr = 0; rr < 16; rr++) {
        int grow = brow + r0 + rr;
        if (grow < N_NODES)
            atomicAdd(&g_h0[(size_t)grow * OUT_CH + c], sum[rr]);
    }
}

// ---------------- APPNP propagation ----------------
template <int SEL>
__device__ __forceinline__ const float* buf_const() {
    return SEL == 0 ? g_h0 : (SEL == 1 ? g_ha : g_hb);
}

// One warp per edge: lane = channel.
template <int CUR>
__global__ void scatter_kernel() {
    const float* __restrict__ h = buf_const<CUR>();
    int t = blockIdx.x * blockDim.x + threadIdx.x;
    int e = t >> 5;
    int lane = t & 31;
    if (e >= N_EDGES) return;
    float v = g_coef[e] * h[(size_t)g_src[e] * OUT_CH + lane];
    atomicAdd(&g_agg[(size_t)g_dst[e] * OUT_CH + lane], v);
}

// h_next = alpha*h0 + (1-alpha)*(agg + h_cur/deg); re-zeroes agg. NXT==3 -> out.
template <int CUR, int NXT>
__global__ void combine_kernel(float* __restrict__ out) {
    const float* __restrict__ h_cur = buf_const<CUR>();
    float* __restrict__ h_next = (NXT == 3) ? out : (NXT == 1 ? g_ha : g_hb);
    int i = blockIdx.x * blockDim.x + threadIdx.x;
    if (i >= N_NODES * OUT_CH) return;
    int node = i >> 5;
    float a = g_agg[i];
    g_agg[i] = 0.0f;
    float self_c = 1.0f / (float)g_deg[node];
    h_next[i] = ALPHA * g_h0[i] + (1.0f - ALPHA) * (a + self_c * h_cur[i]);
}

// ---------------- host launch ----------------
extern "C" void kernel_launch(void* const* d_in, const int* in_sizes, int n_in,
                              void* d_out, int out_size) {
    // Identify inputs by element count (all six are distinct).
    const float* x = nullptr;  const void* ei = nullptr;
    const float* W1 = nullptr; const float* b1 = nullptr;
    const float* W2 = nullptr; const float* b2 = nullptr;
    for (int i = 0; i < n_in; i++) {
        switch (in_sizes[i]) {
            case N_NODES * IN_CH:   x  = (const float*)d_in[i]; break;     // 51,200,000
            case 2 * N_EDGES:       ei = d_in[i]; break;                   // 3,200,000
            case IN_CH * HID_CH:    W1 = (const float*)d_in[i]; break;     // 131,072
            case HID_CH:            b1 = (const float*)d_in[i]; break;     // 256
            case HID_CH * OUT_CH:   W2 = (const float*)d_in[i]; break;     // 8,192
            case OUT_CH:            b2 = (const float*)d_in[i]; break;     // 32
            default: break;
        }
    }
    float* out = (float*)d_out;

    const int NC = N_NODES * OUT_CH;

    // dtype detection + degree + edge norm precompute
    detect_dtype_kernel<<<1, 32>>>((const int*)ei);
    init_deg_kernel<<<(N_NODES + 255) / 256, 256>>>();
    deg_edges_kernel<<<(N_EDGES + 255) / 256, 256>>>(ei);
    precompute_edges_kernel<<<(N_EDGES + 255) / 256, 256>>>(ei);

    // fused MLP: h0 = relu(x@W1+b1)@W2 + b2
    init_h0_bias_kernel<<<(NC + 255) / 256, 256>>>(b2);
    {
        dim3 grid((N_NODES + 127) / 128, HID_CH / 64);
        mlp_fused_kernel<<<grid, 256>>>(x, W1, b1, W2);
    }

    // propagation
    zero_agg_kernel<<<(NC + 255) / 256, 256>>>();

    const int SB = 200000;               // scatter blocks: 1.6M warps / 8
    const int CB = (NC + 255) / 256;

    scatter_kernel<0><<<SB, 256>>>(); combine_kernel<0, 1><<<CB, 256>>>(out); // k=0
    scatter_kernel<1><<<SB, 256>>>(); combine_kernel<1, 2><<<CB, 256>>>(out); // k=1
    scatter_kernel<2><<<SB, 256>>>(); combine_kernel<2, 1><<<CB, 256>>>(out); // k=2
    scatter_kernel<1><<<SB, 256>>>(); combine_kernel<1, 2><<<CB, 256>>>(out); // k=3
    scatter_kernel<2><<<SB, 256>>>(); combine_kernel<2, 1><<<CB, 256>>>(out); // k=4
    scatter_kernel<1><<<SB, 256>>>(); combine_kernel<1, 2><<<CB, 256>>>(out); // k=5
    scatter_kernel<2><<<SB, 256>>>(); combine_kernel<2, 1><<<CB, 256>>>(out); // k=6
    scatter_kernel<1><<<SB, 256>>>(); combine_kernel<1, 2><<<CB, 256>>>(out); // k=7
    scatter_kernel<2><<<SB, 256>>>(); combine_kernel<2, 1><<<CB, 256>>>(out); // k=8
    scatter_kernel<1><<<SB, 256>>>(); combine_kernel<1, 3><<<CB, 256>>>(out); // k=9 -> out
}

// round 5
// speedup vs baseline: 1.6416x; 1.6416x over previous
#include <cuda_runtime.h>
#include <cstdint>

// ---------------- problem constants ----------------
#define N_NODES 100000
#define IN_CH   512
#define HID_CH  256
#define OUT_CH  32
#define N_EDGES 1600000
#define K_STEPS 10
#define ALPHA   0.1f

// ---------------- device scratch (no allocations allowed) ----------------
__device__ float g_h0[(size_t)N_NODES * OUT_CH];   // h0 = relu(x@W1+b1)@W2+b2
__device__ float g_ha[(size_t)N_NODES * OUT_CH];   // ping
__device__ float g_hb[(size_t)N_NODES * OUT_CH];   // pong
__device__ float g_agg[(size_t)N_NODES * OUT_CH];  // per-step scatter accumulator
__device__ int   g_deg[N_NODES];
__device__ float g_selfc[N_NODES];                 // 1/deg
__device__ int4  g_edges[N_EDGES];                 // {src, dst, coef_bits, 0}
__device__ int   g_idx64;                          // 1 if edge_index is int64

// ---------------- dtype detection ----------------
// If edge_index is int64, all high 32-bit words are 0 (indices in [0,1e5)).
// If int32, odd words are random indices -> essentially never all zero.
__global__ void detect_dtype_kernel(const int* __restrict__ ei32) {
    int t = threadIdx.x;
    int any = 0;
    for (int i = t; i < 1024; i += 32) any |= ei32[2 * i + 1];
#pragma unroll
    for (int o = 16; o; o >>= 1) any |= __shfl_xor_sync(0xffffffffu, any, o);
    if (t == 0) g_idx64 = (any == 0) ? 1 : 0;
}

__device__ __forceinline__ int load_idx(const void* ei, size_t pos, int is64) {
    long long v = is64 ? ((const long long*)ei)[pos] : (long long)((const int*)ei)[pos];
    if (v < 0) v = 0;
    if (v >= N_NODES) v = N_NODES - 1;
    return (int)v;
}

// ---------------- degree + edge precompute ----------------
__global__ void init_deg_kernel() {
    int i = blockIdx.x * blockDim.x + threadIdx.x;
    if (i < N_NODES) g_deg[i] = 1;  // self-loop
}

__global__ void deg_edges_kernel(const void* __restrict__ ei) {
    int e = blockIdx.x * blockDim.x + threadIdx.x;
    if (e >= N_EDGES) return;
    int is64 = g_idx64;
    atomicAdd(&g_deg[load_idx(ei, (size_t)N_EDGES + e, is64)], 1);
}

__global__ void selfc_kernel() {
    int i = blockIdx.x * blockDim.x + threadIdx.x;
    if (i < N_NODES) g_selfc[i] = 1.0f / (float)g_deg[i];
}

__global__ void precompute_edges_kernel(const void* __restrict__ ei) {
    int e = blockIdx.x * blockDim.x + threadIdx.x;
    if (e >= N_EDGES) return;
    int is64 = g_idx64;
    int s = load_idx(ei, e, is64);
    int d = load_idx(ei, (size_t)N_EDGES + e, is64);
    float c = rsqrtf((float)g_deg[s]) * rsqrtf((float)g_deg[d]);
    g_edges[e] = make_int4(s, d, __float_as_int(c), 0);
}

__global__ void init_h0_bias_kernel(const float* __restrict__ b2) {
    int i = blockIdx.x * blockDim.x + threadIdx.x;
    if (i < N_NODES * OUT_CH / 4) {
        const float4* b2v = (const float4*)b2;
        ((float4*)g_h0)[i] = b2v[i & 7];
    }
}

__global__ void zero_agg_kernel() {
    int i = blockIdx.x * blockDim.x + threadIdx.x;
    if (i < N_NODES * OUT_CH / 4)
        ((float4*)g_agg)[i] = make_float4(0.f, 0.f, 0.f, 0.f);
}

// ---------------- fused MLP ----------------
// Block: 128 rows x 128 hidden chunk. Stage 1: 128x128 tile of relu(x@W1+b1)
// (8x8 per thread, float4 smem). Stage 2: tile @ W2-slice in two 64-col halves,
// register accumulation, atomic add into g_h0 (preloaded with b2).
__global__ __launch_bounds__(256)
void mlp_fused_kernel(const float* __restrict__ x, const float* __restrict__ W1,
                      const float* __restrict__ b1, const float* __restrict__ W2) {
    union Smem {
        struct { float As[16][128]; float Bs[16][128]; } s1;  // 16 KB
        struct { float Cs[128][68]; float W2s[64][32]; } s2;  // 42.8 KB
    };
    __shared__ Smem u;

    const int tid  = threadIdx.x;
    const int brow = blockIdx.x * 128;
    const int bcol = blockIdx.y * 128;  // hidden-channel chunk
    const int tx = tid % 16;            // column group (8 cols each)
    const int ty = tid / 16;            // row group (8 rows each)

    float acc[8][8];
#pragma unroll
    for (int i = 0; i < 8; i++)
#pragma unroll
        for (int j = 0; j < 8; j++) acc[i][j] = 0.0f;

    // ---- stage 1: 128x128 tile of x@W1, K = 512 in steps of 16 ----
    for (int k0 = 0; k0 < IN_CH; k0 += 16) {
#pragma unroll
        for (int l = 0; l < 2; l++) {          // A: 128x16 = 512 float4
            int idx  = tid + l * 256;
            int row  = idx >> 2;
            int c4   = (idx & 3) * 4;
            int grow = brow + row;
            float4 v = make_float4(0.f, 0.f, 0.f, 0.f);
            if (grow < N_NODES)
                v = *(const float4*)&x[(size_t)grow * IN_CH + k0 + c4];
            u.s1.As[c4 + 0][row] = v.x;
            u.s1.As[c4 + 1][row] = v.y;
            u.s1.As[c4 + 2][row] = v.z;
            u.s1.As[c4 + 3][row] = v.w;
        }
#pragma unroll
        for (int l = 0; l < 2; l++) {          // B: 16x128 = 512 float4
            int idx = tid + l * 256;
            int row = idx >> 5;
            int c4  = (idx & 31) * 4;
            *(float4*)&u.s1.Bs[row][c4] =
                *(const float4*)&W1[(size_t)(k0 + row) * HID_CH + bcol + c4];
        }
        __syncthreads();

#pragma unroll
        for (int k = 0; k < 16; k++) {
            float4 a0 = *(const float4*)&u.s1.As[k][ty * 8];
            float4 a1 = *(const float4*)&u.s1.As[k][ty * 8 + 4];
            float4 b0 = *(const float4*)&u.s1.Bs[k][tx * 8];
            float4 b1v = *(const float4*)&u.s1.Bs[k][tx * 8 + 4];
            float a[8] = {a0.x, a0.y, a0.z, a0.w, a1.x, a1.y, a1.z, a1.w};
            float b[8] = {b0.x, b0.y, b0.z, b0.w, b1v.x, b1v.y, b1v.z, b1v.w};
#pragma unroll
            for (int i = 0; i < 8; i++)
#pragma unroll
                for (int j = 0; j < 8; j++) acc[i][j] += a[i] * b[j];
        }
        __syncthreads();
    }

    // ---- stage 2: relu(acc+b1) @ W2-slice, two 64-col halves ----
    const int c    = tid & 31;   // output channel
    const int rgrp = tid >> 5;   // 0..7, 16 rows each
    float sum[16];
#pragma unroll
    for (int rr = 0; rr < 16; rr++) sum[rr] = 0.0f;

#pragma unroll
    for (int h = 0; h < 2; h++) {
        __syncthreads();  // previous half consumed / stage-1 smem free
        if ((tx >> 3) == h) {
            int cx = (tx & 7) * 8;
#pragma unroll
            for (int i = 0; i < 8; i++) {
#pragma unroll
                for (int j = 0; j < 8; j++) {
                    float v = acc[i][j] + b1[bcol + tx * 8 + j];
                    u.s2.Cs[ty * 8 + i][cx + j] = fmaxf(v, 0.0f);
                }
            }
        }
#pragma unroll
        for (int l = 0; l < 8; l++) {  // W2 slice [64,32]
            int q = tid + l * 256;
            u.s2.W2s[q >> 5][q & 31] =
                W2[(size_t)(bcol + h * 64 + (q >> 5)) * OUT_CH + (q & 31)];
        }
        __syncthreads();

#pragma unroll
        for (int k4 = 0; k4 < 16; k4++) {
            float w0 = u.s2.W2s[k4 * 4 + 0][c];
            float w1 = u.s2.W2s[k4 * 4 + 1][c];
            float w2 = u.s2.W2s[k4 * 4 + 2][c];
            float w3 = u.s2.W2s[k4 * 4 + 3][c];
#pragma unroll
            for (int rr = 0; rr < 16; rr++) {
                float4 cv = *(const float4*)&u.s2.Cs[rgrp * 16 + rr][k4 * 4];
                sum[rr] += cv.x * w0 + cv.y * w1 + cv.z * w2 + cv.w * w3;
            }
        }
    }

#pragma unroll
    for (int rr = 0; rr < 16; rr++) {
        int grow = brow + rgrp * 16 + rr;
        if (grow < N_NODES)
            atomicAdd(&g_h0[(size_t)grow * OUT_CH + c], sum[rr]);
    }
}

// ---------------- APPNP propagation ----------------
template <int SEL>
__device__ __forceinline__ const float* buf_const() {
    return SEL == 0 ? g_h0 : (SEL == 1 ? g_ha : g_hb);
}

// 8 lanes per edge: lane q handles channels [4q, 4q+4). float4 gather + red.v4.
template <int CUR>
__global__ void scatter_kernel() {
    const float* __restrict__ h = buf_const<CUR>();
    int t = blockIdx.x * blockDim.x + threadIdx.x;
    int e = t >> 3;
    int q = t & 7;
    if (e >= N_EDGES) return;
    int4 ed = g_edges[e];
    float cf = __int_as_float(ed.z);
    float4 hv = *(const float4*)&h[(size_t)ed.x * OUT_CH + q * 4];
    float* dst = &g_agg[(size_t)ed.y * OUT_CH + q * 4];
    asm volatile("red.global.add.v4.f32 [%0], {%1, %2, %3, %4};"
                 :: "l"(dst), "f"(hv.x * cf), "f"(hv.y * cf),
                    "f"(hv.z * cf), "f"(hv.w * cf)
                 : "memory");
}

// h_next = alpha*h0 + (1-alpha)*(agg + selfc*h_cur); re-zeroes agg. NXT==3 -> out.
template <int CUR, int NXT>
__global__ void combine_kernel(float* __restrict__ out) {
    const float4* __restrict__ h_cur = (const float4*)buf_const<CUR>();
    float4* __restrict__ h_next =
        (NXT == 3) ? (float4*)out : (NXT == 1 ? (float4*)g_ha : (float4*)g_hb);
    int i = blockIdx.x * blockDim.x + threadIdx.x;
    if (i >= N_NODES * OUT_CH / 4) return;
    int node = i >> 3;
    float4* aggv = (float4*)g_agg;
    float4 a = aggv[i];
    aggv[i] = make_float4(0.f, 0.f, 0.f, 0.f);
    float sc = g_selfc[node];
    float4 hc = h_cur[i];
    float4 h0v = ((const float4*)g_h0)[i];
    float4 r;
    r.x = ALPHA * h0v.x + (1.0f - ALPHA) * (a.x + sc * hc.x);
    r.y = ALPHA * h0v.y + (1.0f - ALPHA) * (a.y + sc * hc.y);
    r.z = ALPHA * h0v.z + (1.0f - ALPHA) * (a.z + sc * hc.z);
    r.w = ALPHA * h0v.w + (1.0f - ALPHA) * (a.w + sc * hc.w);
    h_next[i] = r;
}

// ---------------- host launch ----------------
extern "C" void kernel_launch(void* const* d_in, const int* in_sizes, int n_in,
                              void* d_out, int out_size) {
    // Identify inputs by element count (all six are distinct).
    const float* x = nullptr;  const void* ei = nullptr;
    const float* W1 = nullptr; const float* b1 = nullptr;
    const float* W2 = nullptr; const float* b2 = nullptr;
    for (int i = 0; i < n_in; i++) {
        switch (in_sizes[i]) {
            case N_NODES * IN_CH:   x  = (const float*)d_in[i]; break;     // 51,200,000
            case 2 * N_EDGES:       ei = d_in[i]; break;                   // 3,200,000
            case IN_CH * HID_CH:    W1 = (const float*)d_in[i]; break;     // 131,072
            case HID_CH:            b1 = (const float*)d_in[i]; break;     // 256
            case HID_CH * OUT_CH:   W2 = (const float*)d_in[i]; break;     // 8,192
            case OUT_CH:            b2 = (const float*)d_in[i]; break;     // 32
            default: break;
        }
    }
    float* out = (float*)d_out;

    const int NC  = N_NODES * OUT_CH;
    const int NC4 = NC / 4;

    // dtype detection + degree + edge norm precompute
    detect_dtype_kernel<<<1, 32>>>((const int*)ei);
    init_deg_kernel<<<(N_NODES + 255) / 256, 256>>>();
    deg_edges_kernel<<<(N_EDGES + 255) / 256, 256>>>(ei);
    selfc_kernel<<<(N_NODES + 255) / 256, 256>>>();
    precompute_edges_kernel<<<(N_EDGES + 255) / 256, 256>>>(ei);

    // fused MLP: h0 = relu(x@W1+b1)@W2 + b2
    init_h0_bias_kernel<<<(NC4 + 255) / 256, 256>>>(b2);
    {
        dim3 grid((N_NODES + 127) / 128, HID_CH / 128);
        mlp_fused_kernel<<<grid, 256>>>(x, W1, b1, W2);
    }

    // propagation
    zero_agg_kernel<<<(NC4 + 255) / 256, 256>>>();

    const int SB = (int)(((size_t)N_EDGES * 8 + 255) / 256);  // 50000
    const int CB = (NC4 + 255) / 256;

    scatter_kernel<0><<<SB, 256>>>(); combine_kernel<0, 1><<<CB, 256>>>(out); // k=0
    scatter_kernel<1><<<SB, 256>>>(); combine_kernel<1, 2><<<CB, 256>>>(out); // k=1
    scatter_kernel<2><<<SB, 256>>>(); combine_kernel<2, 1><<<CB, 256>>>(out); // k=2
    scatter_kernel<1><<<SB, 256>>>(); combine_kernel<1, 2><<<CB, 256>>>(out); // k=3
    scatter_kernel<2><<<SB, 256>>>(); combine_kernel<2, 1><<<CB, 256>>>(out); // k=4
    scatter_kernel<1><<<SB, 256>>>(); combine_kernel<1, 2><<<CB, 256>>>(out); // k=5
    scatter_kernel<2><<<SB, 256>>>(); combine_kernel<2, 1><<<CB, 256>>>(out); // k=6
    scatter_kernel<1><<<SB, 256>>>(); combine_kernel<1, 2><<<CB, 256>>>(out); // k=7
    scatter_kernel<2><<<SB, 256>>>(); combine_kernel<2, 1><<<CB, 256>>>(out); // k=8
    scatter_kernel<1><<<SB, 256>>>(); combine_kernel<1, 3><<<CB, 256>>>(out); // k=9 -> out
}

// round 6
// speedup vs baseline: 2.3018x; 1.4022x over previous
#include <cuda_runtime.h>
#include <cuda_bf16.h>
#include <cstdint>

// ---------------- problem constants ----------------
#define N_NODES 100000
#define IN_CH   512
#define HID_CH  256
#define OUT_CH  32
#define N_EDGES 1600000
#define K_STEPS 10
#define ALPHA   0.1f

// ---------------- device scratch (no allocations allowed) ----------------
__device__ float g_h0[(size_t)N_NODES * OUT_CH];
__device__ float g_ha[(size_t)N_NODES * OUT_CH];
__device__ float g_hb[(size_t)N_NODES * OUT_CH];
__device__ float g_agg[(size_t)N_NODES * OUT_CH];
__device__ int   g_deg[N_NODES];
__device__ float g_selfc[N_NODES];
__device__ int4  g_edges[N_EDGES];
__device__ int   g_idx64;

// split-bf16 operands for the tensor-core GEMM
__device__ __align__(16) __nv_bfloat16 g_xh[(size_t)N_NODES * IN_CH];
__device__ __align__(16) __nv_bfloat16 g_xl[(size_t)N_NODES * IN_CH];
__device__ __align__(16) __nv_bfloat16 g_w1t_h[(size_t)HID_CH * IN_CH];  // [n][k]
__device__ __align__(16) __nv_bfloat16 g_w1t_l[(size_t)HID_CH * IN_CH];

// ---------------- dtype detection ----------------
__global__ void detect_dtype_kernel(const int* __restrict__ ei32) {
    int t = threadIdx.x;
    int any = 0;
    for (int i = t; i < 1024; i += 32) any |= ei32[2 * i + 1];
#pragma unroll
    for (int o = 16; o; o >>= 1) any |= __shfl_xor_sync(0xffffffffu, any, o);
    if (t == 0) g_idx64 = (any == 0) ? 1 : 0;
}

__device__ __forceinline__ int load_idx(const void* ei, size_t pos, int is64) {
    long long v = is64 ? ((const long long*)ei)[pos] : (long long)((const int*)ei)[pos];
    if (v < 0) v = 0;
    if (v >= N_NODES) v = N_NODES - 1;
    return (int)v;
}

// ---------------- degree + edge precompute ----------------
__global__ void init_deg_kernel() {
    int i = blockIdx.x * blockDim.x + threadIdx.x;
    if (i < N_NODES) g_deg[i] = 1;
}

__global__ void deg_edges_kernel(const void* __restrict__ ei) {
    int e = blockIdx.x * blockDim.x + threadIdx.x;
    if (e >= N_EDGES) return;
    int is64 = g_idx64;
    atomicAdd(&g_deg[load_idx(ei, (size_t)N_EDGES + e, is64)], 1);
}

__global__ void selfc_kernel() {
    int i = blockIdx.x * blockDim.x + threadIdx.x;
    if (i < N_NODES) g_selfc[i] = 1.0f / (float)g_deg[i];
}

__global__ void precompute_edges_kernel(const void* __restrict__ ei) {
    int e = blockIdx.x * blockDim.x + threadIdx.x;
    if (e >= N_EDGES) return;
    int is64 = g_idx64;
    int s = load_idx(ei, e, is64);
    int d = load_idx(ei, (size_t)N_EDGES + e, is64);
    float c = rsqrtf((float)g_deg[s]) * rsqrtf((float)g_deg[d]);
    g_edges[e] = make_int4(s, d, __float_as_int(c), 0);
}

__global__ void init_h0_bias_kernel(const float* __restrict__ b2) {
    int i = blockIdx.x * blockDim.x + threadIdx.x;
    if (i < N_NODES * OUT_CH / 4) {
        const float4* b2v = (const float4*)b2;
        ((float4*)g_h0)[i] = b2v[i & 7];
    }
}

__global__ void zero_agg_kernel() {
    int i = blockIdx.x * blockDim.x + threadIdx.x;
    if (i < N_NODES * OUT_CH / 4)
        ((float4*)g_agg)[i] = make_float4(0.f, 0.f, 0.f, 0.f);
}

// ---------------- split-precision conversion ----------------
__device__ __forceinline__ void split1(float v, unsigned short& h, unsigned short& l) {
    __nv_bfloat16 hb = __float2bfloat16(v);
    float r = v - __bfloat162float(hb);
    __nv_bfloat16 lb = __float2bfloat16(r);
    h = *(unsigned short*)&hb;
    l = *(unsigned short*)&lb;
}

__global__ void split_x_kernel(const float* __restrict__ x) {
    int i = blockIdx.x * blockDim.x + threadIdx.x;  // one float4 per thread
    if (i >= N_NODES * IN_CH / 4) return;
    float4 v = ((const float4*)x)[i];
    ushort4 hh, ll;
    split1(v.x, hh.x, ll.x);
    split1(v.y, hh.y, ll.y);
    split1(v.z, hh.z, ll.z);
    split1(v.w, hh.w, ll.w);
    ((ushort4*)g_xh)[i] = hh;
    ((ushort4*)g_xl)[i] = ll;
}

__global__ void split_w1t_kernel(const float* __restrict__ W1) {
    int i = blockIdx.x * blockDim.x + threadIdx.x;
    if (i >= HID_CH * IN_CH) return;
    int n = i >> 9;         // hidden channel
    int k = i & 511;        // input channel
    unsigned short h, l;
    split1(W1[(size_t)k * HID_CH + n], h, l);
    ((unsigned short*)g_w1t_h)[i] = h;
    ((unsigned short*)g_w1t_l)[i] = l;
}

// ---------------- tensor-core fused MLP ----------------
#define MMA_BF16(d, a, b0v, b1v)                                             \
    asm volatile(                                                            \
        "mma.sync.aligned.m16n8k16.row.col.f32.bf16.bf16.f32 "               \
        "{%0,%1,%2,%3}, {%4,%5,%6,%7}, {%8,%9}, {%0,%1,%2,%3};"              \
        : "+f"(d[0]), "+f"(d[1]), "+f"(d[2]), "+f"(d[3])                     \
        : "r"(a[0]), "r"(a[1]), "r"(a[2]), "r"(a[3]), "r"(b0v), "r"(b1v))

#define APITCH 40   // bf16 elements per smem row (32 + 8 pad)
#define CPITCH 68   // fp32 elements per Cs row

__global__ __launch_bounds__(256, 2)
void mlp_mma_kernel(const float* __restrict__ b1, const float* __restrict__ W2) {
    __shared__ __align__(16) union {
        struct {
            __nv_bfloat16 Ah[128 * APITCH], Al[128 * APITCH];
            __nv_bfloat16 Bh[128 * APITCH], Bl[128 * APITCH];
        } s1;                                        // 40 KB
        struct { float Cs[128 * CPITCH]; float W2s[64 * 32]; } s2;  // 42.8 KB
    } u;

    const int tid  = threadIdx.x;
    const int warp = tid >> 5;
    const int lane = tid & 31;
    const int wm = warp >> 1;          // 0..3  (32-row slab)
    const int wn = warp & 1;           // 0..1  (64-col slab)
    const int g  = lane >> 2;          // 0..7
    const int t  = lane & 3;           // 0..3
    const int brow = blockIdx.x * 128;
    const int bcol = blockIdx.y * 128;

    float acc[2][8][4];
#pragma unroll
    for (int i = 0; i < 2; i++)
#pragma unroll
        for (int j = 0; j < 8; j++)
#pragma unroll
            for (int r = 0; r < 4; r++) acc[i][j][r] = 0.0f;

    const uint4 zero4 = make_uint4(0, 0, 0, 0);

    for (int k0 = 0; k0 < IN_CH; k0 += 32) {
        // ---- stage tiles: A (x rows) and B (W1^T rows), hi+lo ----
#pragma unroll
        for (int l = 0; l < 2; l++) {
            int idx = tid + l * 256;
            int row = idx >> 2;
            int seg = idx & 3;
            size_t go = (size_t)(brow + row) * IN_CH + k0 + seg * 8;
            uint4 vh = zero4, vl = zero4;
            if (brow + row < N_NODES) {
                vh = *(const uint4*)&g_xh[go];
                vl = *(const uint4*)&g_xl[go];
            }
            *(uint4*)&u.s1.Ah[row * APITCH + seg * 8] = vh;
            *(uint4*)&u.s1.Al[row * APITCH + seg * 8] = vl;
        }
#pragma unroll
        for (int l = 0; l < 2; l++) {
            int idx = tid + l * 256;
            int row = idx >> 2;   // n index within tile
            int seg = idx & 3;
            size_t go = (size_t)(bcol + row) * IN_CH + k0 + seg * 8;
            *(uint4*)&u.s1.Bh[row * APITCH + seg * 8] = *(const uint4*)&g_w1t_h[go];
            *(uint4*)&u.s1.Bl[row * APITCH + seg * 8] = *(const uint4*)&g_w1t_l[go];
        }
        __syncthreads();

#pragma unroll
        for (int kk = 0; kk < 32; kk += 16) {
            uint32_t ah[2][4], al[2][4];
#pragma unroll
            for (int i = 0; i < 2; i++) {
                int r = wm * 32 + i * 16 + g;
                int base = r * APITCH + kk + t * 2;
                ah[i][0] = *(const uint32_t*)&u.s1.Ah[base];
                ah[i][1] = *(const uint32_t*)&u.s1.Ah[base + 8 * APITCH];
                ah[i][2] = *(const uint32_t*)&u.s1.Ah[base + 8];
                ah[i][3] = *(const uint32_t*)&u.s1.Ah[base + 8 * APITCH + 8];
                al[i][0] = *(const uint32_t*)&u.s1.Al[base];
                al[i][1] = *(const uint32_t*)&u.s1.Al[base + 8 * APITCH];
                al[i][2] = *(const uint32_t*)&u.s1.Al[base + 8];
                al[i][3] = *(const uint32_t*)&u.s1.Al[base + 8 * APITCH + 8];
            }
#pragma unroll
            for (int j = 0; j < 8; j++) {
                int n = wn * 64 + j * 8 + g;
                int bb = n * APITCH + kk + t * 2;
                uint32_t bh0 = *(const uint32_t*)&u.s1.Bh[bb];
                uint32_t bh1 = *(const uint32_t*)&u.s1.Bh[bb + 8];
                uint32_t bl0 = *(const uint32_t*)&u.s1.Bl[bb];
                uint32_t bl1 = *(const uint32_t*)&u.s1.Bl[bb + 8];
#pragma unroll
                for (int i = 0; i < 2; i++) {
                    MMA_BF16(acc[i][j], ah[i], bh0, bh1);
                    MMA_BF16(acc[i][j], ah[i], bl0, bl1);
                    MMA_BF16(acc[i][j], al[i], bh0, bh1);
                }
            }
        }
        __syncthreads();
    }

    // ---- stage 2: relu(acc + b1) @ W2-slice, two 64-col halves ----
    const int c    = tid & 31;
    const int rgrp = tid >> 5;
    float sum[16];
#pragma unroll
    for (int rr = 0; rr < 16; rr++) sum[rr] = 0.0f;

#pragma unroll
    for (int h = 0; h < 2; h++) {
        __syncthreads();
        if (wn == h) {
#pragma unroll
            for (int i = 0; i < 2; i++)
#pragma unroll
                for (int j = 0; j < 8; j++) {
                    int row = wm * 32 + i * 16 + g;
                    int col = j * 8 + t * 2;  // within half
                    float bias0 = b1[bcol + h * 64 + col];
                    float bias1 = b1[bcol + h * 64 + col + 1];
                    float2 v0, v1;
                    v0.x = fmaxf(acc[i][j][0] + bias0, 0.0f);
                    v0.y = fmaxf(acc[i][j][1] + bias1, 0.0f);
                    v1.x = fmaxf(acc[i][j][2] + bias0, 0.0f);
                    v1.y = fmaxf(acc[i][j][3] + bias1, 0.0f);
                    *(float2*)&u.s2.Cs[row * CPITCH + col]       = v0;
                    *(float2*)&u.s2.Cs[(row + 8) * CPITCH + col] = v1;
                }
        }
#pragma unroll
        for (int l = 0; l < 8; l++) {  // W2 slice [64,32]
            int q = tid + l * 256;
            u.s2.W2s[q] = W2[(size_t)(bcol + h * 64 + (q >> 5)) * OUT_CH + (q & 31)];
        }
        __syncthreads();

#pragma unroll
        for (int k4 = 0; k4 < 16; k4++) {
            float w0 = u.s2.W2s[(k4 * 4 + 0) * 32 + c];
            float w1 = u.s2.W2s[(k4 * 4 + 1) * 32 + c];
            float w2 = u.s2.W2s[(k4 * 4 + 2) * 32 + c];
            float w3 = u.s2.W2s[(k4 * 4 + 3) * 32 + c];
#pragma unroll
            for (int rr = 0; rr < 16; rr++) {
                float4 cv = *(const float4*)&u.s2.Cs[(rgrp * 16 + rr) * CPITCH + k4 * 4];
                sum[rr] += cv.x * w0 + cv.y * w1 + cv.z * w2 + cv.w * w3;
            }
        }
    }

#pragma unroll
    for (int rr = 0; rr < 16; rr++) {
        int grow = brow + rgrp * 16 + rr;
        if (grow < N_NODES)
            atomicAdd(&g_h0[(size_t)grow * OUT_CH + c], sum[rr]);
    }
}

// ---------------- APPNP propagation ----------------
template <int SEL>
__device__ __forceinline__ const float* buf_const() {
    return SEL == 0 ? g_h0 : (SEL == 1 ? g_ha : g_hb);
}

template <int CUR>
__global__ void scatter_kernel() {
    const float* __restrict__ h = buf_const<CUR>();
    int t = blockIdx.x * blockDim.x + threadIdx.x;
    int e = t >> 3;
    int q = t & 7;
    if (e >= N_EDGES) return;
    int4 ed = g_edges[e];
    float cf = __int_as_float(ed.z);
    float4 hv = *(const float4*)&h[(size_t)ed.x * OUT_CH + q * 4];
    float* dst = &g_agg[(size_t)ed.y * OUT_CH + q * 4];
    asm volatile("red.global.add.v4.f32 [%0], {%1, %2, %3, %4};"
                 :: "l"(dst), "f"(hv.x * cf), "f"(hv.y * cf),
                    "f"(hv.z * cf), "f"(hv.w * cf)
                 : "memory");
}

template <int CUR, int NXT>
__global__ void combine_kernel(float* __restrict__ out) {
    const float4* __restrict__ h_cur = (const float4*)buf_const<CUR>();
    float4* __restrict__ h_next =
        (NXT == 3) ? (float4*)out : (NXT == 1 ? (float4*)g_ha : (float4*)g_hb);
    int i = blockIdx.x * blockDim.x + threadIdx.x;
    if (i >= N_NODES * OUT_CH / 4) return;
    int node = i >> 3;
    float4* aggv = (float4*)g_agg;
    float4 a = aggv[i];
    aggv[i] = make_float4(0.f, 0.f, 0.f, 0.f);
    float sc = g_selfc[node];
    float4 hc = h_cur[i];
    float4 h0v = ((const float4*)g_h0)[i];
    float4 r;
    r.x = ALPHA * h0v.x + (1.0f - ALPHA) * (a.x + sc * hc.x);
    r.y = ALPHA * h0v.y + (1.0f - ALPHA) * (a.y + sc * hc.y);
    r.z = ALPHA * h0v.z + (1.0f - ALPHA) * (a.z + sc * hc.z);
    r.w = ALPHA * h0v.w + (1.0f - ALPHA) * (a.w + sc * hc.w);
    h_next[i] = r;
}

// ---------------- host launch ----------------
extern "C" void kernel_launch(void* const* d_in, const int* in_sizes, int n_in,
                              void* d_out, int out_size) {
    const float* x = nullptr;  const void* ei = nullptr;
    const float* W1 = nullptr; const float* b1 = nullptr;
    const float* W2 = nullptr; const float* b2 = nullptr;
    for (int i = 0; i < n_in; i++) {
        switch (in_sizes[i]) {
            case N_NODES * IN_CH:   x  = (const float*)d_in[i]; break;
            case 2 * N_EDGES:       ei = d_in[i]; break;
            case IN_CH * HID_CH:    W1 = (const float*)d_in[i]; break;
            case HID_CH:            b1 = (const float*)d_in[i]; break;
            case HID_CH * OUT_CH:   W2 = (const float*)d_in[i]; break;
            case OUT_CH:            b2 = (const float*)d_in[i]; break;
            default: break;
        }
    }
    float* out = (float*)d_out;

    const int NC4 = N_NODES * OUT_CH / 4;

    detect_dtype_kernel<<<1, 32>>>((const int*)ei);
    init_deg_kernel<<<(N_NODES + 255) / 256, 256>>>();
    deg_edges_kernel<<<(N_EDGES + 255) / 256, 256>>>(ei);
    selfc_kernel<<<(N_NODES + 255) / 256, 256>>>();
    precompute_edges_kernel<<<(N_EDGES + 255) / 256, 256>>>(ei);

    // split-precision operand prep
    split_x_kernel<<<(N_NODES * IN_CH / 4 + 255) / 256, 256>>>(x);
    split_w1t_kernel<<<(HID_CH * IN_CH + 255) / 256, 256>>>(W1);

    // fused MLP: h0 = relu(x@W1+b1)@W2 + b2   (tensor cores, split-bf16)
    init_h0_bias_kernel<<<(NC4 + 255) / 256, 256>>>(b2);
    {
        dim3 grid((N_NODES + 127) / 128, HID_CH / 128);
        mlp_mma_kernel<<<grid, 256>>>(b1, W2);
    }

    // propagation
    zero_agg_kernel<<<(NC4 + 255) / 256, 256>>>();

    const int SB = (int)(((size_t)N_EDGES * 8 + 255) / 256);
    const int CB = (NC4 + 255) / 256;

    scatter_kernel<0><<<SB, 256>>>(); combine_kernel<0, 1><<<CB, 256>>>(out); // k=0
    scatter_kernel<1><<<SB, 256>>>(); combine_kernel<1, 2><<<CB, 256>>>(out); // k=1
    scatter_kernel<2><<<SB, 256>>>(); combine_kernel<2, 1><<<CB, 256>>>(out); // k=2
    scatter_kernel<1><<<SB, 256>>>(); combine_kernel<1, 2><<<CB, 256>>>(out); // k=3
    scatter_kernel<2><<<SB, 256>>>(); combine_kernel<2, 1><<<CB, 256>>>(out); // k=4
    scatter_kernel<1><<<SB, 256>>>(); combine_kernel<1, 2><<<CB, 256>>>(out); // k=5
    scatter_kernel<2><<<SB, 256>>>(); combine_kernel<2, 1><<<CB, 256>>>(out); // k=6
    scatter_kernel<1><<<SB, 256>>>(); combine_kernel<1, 2><<<CB, 256>>>(out); // k=7
    scatter_kernel<2><<<SB, 256>>>(); combine_kernel<2, 1><<<CB, 256>>>(out); // k=8
    scatter_kernel<1><<<SB, 256>>>(); combine_kernel<1, 3><<<CB, 256>>>(out); // k=9
}

// round 7
// speedup vs baseline: 3.3803x; 1.4686x over previous
#include <cuda_runtime.h>
#include <cuda_bf16.h>
#include <cstdint>

// ---------------- problem constants ----------------
#define N_NODES 100000
#define IN_CH   512
#define HID_CH  256
#define OUT_CH  32
#define N_EDGES 1600000
#define K_STEPS 10
#define ALPHA   0.1f

// ---------------- device scratch (no allocations allowed) ----------------
__device__ float g_h0[(size_t)N_NODES * OUT_CH];
__device__ float g_ha[(size_t)N_NODES * OUT_CH];
__device__ float g_hb[(size_t)N_NODES * OUT_CH];
__device__ int   g_deg[N_NODES];
__device__ float g_selfc[N_NODES];
__device__ int4  g_edges[N_EDGES];     // {src, dst, coef_bits, 0}
__device__ int   g_idx64;

// CSR (dst-sorted) for pull aggregation
__device__ int   g_rowptr[N_NODES + 1];
__device__ int   g_fill[N_NODES];
__device__ int   g_partial[256];
__device__ int2  g_csr[N_EDGES];       // {src, coef_bits}

// split-bf16 operands for the tensor-core GEMM
__device__ __align__(16) __nv_bfloat16 g_xh[(size_t)N_NODES * IN_CH];
__device__ __align__(16) __nv_bfloat16 g_xl[(size_t)N_NODES * IN_CH];
__device__ __align__(16) __nv_bfloat16 g_w1t_h[(size_t)HID_CH * IN_CH];  // [n][k]
__device__ __align__(16) __nv_bfloat16 g_w1t_l[(size_t)HID_CH * IN_CH];

// ---------------- dtype detection ----------------
__global__ void detect_dtype_kernel(const int* __restrict__ ei32) {
    int t = threadIdx.x;
    int any = 0;
    for (int i = t; i < 1024; i += 32) any |= ei32[2 * i + 1];
#pragma unroll
    for (int o = 16; o; o >>= 1) any |= __shfl_xor_sync(0xffffffffu, any, o);
    if (t == 0) g_idx64 = (any == 0) ? 1 : 0;
}

__device__ __forceinline__ int load_idx(const void* ei, size_t pos, int is64) {
    long long v = is64 ? ((const long long*)ei)[pos] : (long long)((const int*)ei)[pos];
    if (v < 0) v = 0;
    if (v >= N_NODES) v = N_NODES - 1;
    return (int)v;
}

// ---------------- degree + edge precompute ----------------
__global__ void init_deg_kernel() {
    int i = blockIdx.x * blockDim.x + threadIdx.x;
    if (i < N_NODES) g_deg[i] = 1;
}

__global__ void deg_edges_kernel(const void* __restrict__ ei) {
    int e = blockIdx.x * blockDim.x + threadIdx.x;
    if (e >= N_EDGES) return;
    int is64 = g_idx64;
    atomicAdd(&g_deg[load_idx(ei, (size_t)N_EDGES + e, is64)], 1);
}

__global__ void selfc_kernel() {
    int i = blockIdx.x * blockDim.x + threadIdx.x;
    if (i < N_NODES) g_selfc[i] = 1.0f / (float)g_deg[i];
}

__global__ void precompute_edges_kernel(const void* __restrict__ ei) {
    int e = blockIdx.x * blockDim.x + threadIdx.x;
    if (e >= N_EDGES) return;
    int is64 = g_idx64;
    int s = load_idx(ei, e, is64);
    int d = load_idx(ei, (size_t)N_EDGES + e, is64);
    float c = rsqrtf((float)g_deg[s]) * rsqrtf((float)g_deg[d]);
    g_edges[e] = make_int4(s, d, __float_as_int(c), 0);
}

// ---------------- CSR build: 3-kernel exclusive scan + slot fill ----------------
#define SCAN_BLK 512
__global__ void scanA_kernel() {   // per-block exclusive scan of (deg-1)
    __shared__ int s[SCAN_BLK];
    int t = threadIdx.x;
    int i = blockIdx.x * SCAN_BLK + t;
    int v = (i < N_NODES) ? (g_deg[i] - 1) : 0;
    s[t] = v;
    __syncthreads();
#pragma unroll
    for (int off = 1; off < SCAN_BLK; off <<= 1) {
        int x = (t >= off) ? s[t - off] : 0;
        __syncthreads();
        s[t] += x;
        __syncthreads();
    }
    if (i < N_NODES) g_rowptr[i] = s[t] - v;   // exclusive within block
    if (t == SCAN_BLK - 1) g_partial[blockIdx.x] = s[t];
}

__global__ void scanB_kernel(int nblocks) {    // single block scans partials
    __shared__ int s[256];
    int t = threadIdx.x;
    int v = (t < nblocks) ? g_partial[t] : 0;
    s[t] = v;
    __syncthreads();
#pragma unroll
    for (int off = 1; off < 256; off <<= 1) {
        int x = (t >= off) ? s[t - off] : 0;
        __syncthreads();
        s[t] += x;
        __syncthreads();
    }
    if (t < nblocks) g_partial[t] = s[t] - v;  // exclusive
}

__global__ void scanC_kernel() {               // add block offsets, zero fill
    int i = blockIdx.x * blockDim.x + threadIdx.x;
    if (i < N_NODES) {
        g_rowptr[i] += g_partial[i / SCAN_BLK];
        g_fill[i] = 0;
    }
    if (i == 0) g_rowptr[N_NODES] = N_EDGES;
}

__global__ void csr_fill_kernel() {
    int e = blockIdx.x * blockDim.x + threadIdx.x;
    if (e >= N_EDGES) return;
    int4 ed = g_edges[e];
    int pos = g_rowptr[ed.y] + atomicAdd(&g_fill[ed.y], 1);
    g_csr[pos] = make_int2(ed.x, ed.z);
}

__global__ void init_h0_bias_kernel(const float* __restrict__ b2) {
    int i = blockIdx.x * blockDim.x + threadIdx.x;
    if (i < N_NODES * OUT_CH / 4) {
        const float4* b2v = (const float4*)b2;
        ((float4*)g_h0)[i] = b2v[i & 7];
    }
}

// ---------------- split-precision conversion ----------------
__device__ __forceinline__ void split1(float v, unsigned short& h, unsigned short& l) {
    __nv_bfloat16 hb = __float2bfloat16(v);
    float r = v - __bfloat162float(hb);
    __nv_bfloat16 lb = __float2bfloat16(r);
    h = *(unsigned short*)&hb;
    l = *(unsigned short*)&lb;
}

__global__ void split_x_kernel(const float* __restrict__ x) {
    int i = blockIdx.x * blockDim.x + threadIdx.x;
    if (i >= N_NODES * IN_CH / 4) return;
    float4 v = ((const float4*)x)[i];
    ushort4 hh, ll;
    split1(v.x, hh.x, ll.x);
    split1(v.y, hh.y, ll.y);
    split1(v.z, hh.z, ll.z);
    split1(v.w, hh.w, ll.w);
    ((ushort4*)g_xh)[i] = hh;
    ((ushort4*)g_xl)[i] = ll;
}

__global__ void split_w1t_kernel(const float* __restrict__ W1) {
    int i = blockIdx.x * blockDim.x + threadIdx.x;
    if (i >= HID_CH * IN_CH) return;
    int n = i >> 9;
    int k = i & 511;
    unsigned short h, l;
    split1(W1[(size_t)k * HID_CH + n], h, l);
    ((unsigned short*)g_w1t_h)[i] = h;
    ((unsigned short*)g_w1t_l)[i] = l;
}

// ---------------- tensor-core fused MLP ----------------
#define MMA_BF16(d, a, b0v, b1v)                                             \
    asm volatile(                                                            \
        "mma.sync.aligned.m16n8k16.row.col.f32.bf16.bf16.f32 "               \
        "{%0,%1,%2,%3}, {%4,%5,%6,%7}, {%8,%9}, {%0,%1,%2,%3};"              \
        : "+f"(d[0]), "+f"(d[1]), "+f"(d[2]), "+f"(d[3])                     \
        : "r"(a[0]), "r"(a[1]), "r"(a[2]), "r"(a[3]), "r"(b0v), "r"(b1v))

#define APITCH 40
#define CPITCH 68

__global__ __launch_bounds__(256, 2)
void mlp_mma_kernel(const float* __restrict__ b1, const float* __restrict__ W2) {
    __shared__ __align__(16) union {
        struct {
            __nv_bfloat16 Ah[128 * APITCH], Al[128 * APITCH];
            __nv_bfloat16 Bh[128 * APITCH], Bl[128 * APITCH];
        } s1;
        struct { float Cs[128 * CPITCH]; float W2s[64 * 32]; } s2;
    } u;

    const int tid  = threadIdx.x;
    const int warp = tid >> 5;
    const int lane = tid & 31;
    const int wm = warp >> 1;
    const int wn = warp & 1;
    const int g  = lane >> 2;
    const int t  = lane & 3;
    const int brow = blockIdx.x * 128;
    const int bcol = blockIdx.y * 128;

    float acc[2][8][4];
#pragma unroll
    for (int i = 0; i < 2; i++)
#pragma unroll
        for (int j = 0; j < 8; j++)
#pragma unroll
            for (int r = 0; r < 4; r++) acc[i][j][r] = 0.0f;

    const uint4 zero4 = make_uint4(0, 0, 0, 0);

    for (int k0 = 0; k0 < IN_CH; k0 += 32) {
#pragma unroll
        for (int l = 0; l < 2; l++) {
            int idx = tid + l * 256;
            int row = idx >> 2;
            int seg = idx & 3;
            size_t go = (size_t)(brow + row) * IN_CH + k0 + seg * 8;
            uint4 vh = zero4, vl = zero4;
            if (brow + row < N_NODES) {
                vh = *(const uint4*)&g_xh[go];
                vl = *(const uint4*)&g_xl[go];
            }
            *(uint4*)&u.s1.Ah[row * APITCH + seg * 8] = vh;
            *(uint4*)&u.s1.Al[row * APITCH + seg * 8] = vl;
        }
#pragma unroll
        for (int l = 0; l < 2; l++) {
            int idx = tid + l * 256;
            int row = idx >> 2;
            int seg = idx & 3;
            size_t go = (size_t)(bcol + row) * IN_CH + k0 + seg * 8;
            *(uint4*)&u.s1.Bh[row * APITCH + seg * 8] = *(const uint4*)&g_w1t_h[go];
            *(uint4*)&u.s1.Bl[row * APITCH + seg * 8] = *(const uint4*)&g_w1t_l[go];
        }
        __syncthreads();

#pragma unroll
        for (int kk = 0; kk < 32; kk += 16) {
            uint32_t ah[2][4], al[2][4];
#pragma unroll
            for (int i = 0; i < 2; i++) {
                int r = wm * 32 + i * 16 + g;
                int base = r * APITCH + kk + t * 2;
                ah[i][0] = *(const uint32_t*)&u.s1.Ah[base];
                ah[i][1] = *(const uint32_t*)&u.s1.Ah[base + 8 * APITCH];
                ah[i][2] = *(const uint32_t*)&u.s1.Ah[base + 8];
                ah[i][3] = *(const uint32_t*)&u.s1.Ah[base + 8 * APITCH + 8];
                al[i][0] = *(const uint32_t*)&u.s1.Al[base];
                al[i][1] = *(const uint32_t*)&u.s1.Al[base + 8 * APITCH];
                al[i][2] = *(const uint32_t*)&u.s1.Al[base + 8];
                al[i][3] = *(const uint32_t*)&u.s1.Al[base + 8 * APITCH + 8];
            }
#pragma unroll
            for (int j = 0; j < 8; j++) {
                int n = wn * 64 + j * 8 + g;
                int bb = n * APITCH + kk + t * 2;
                uint32_t bh0 = *(const uint32_t*)&u.s1.Bh[bb];
                uint32_t bh1 = *(const uint32_t*)&u.s1.Bh[bb + 8];
                uint32_t bl0 = *(const uint32_t*)&u.s1.Bl[bb];
                uint32_t bl1 = *(const uint32_t*)&u.s1.Bl[bb + 8];
#pragma unroll
                for (int i = 0; i < 2; i++) {
                    MMA_BF16(acc[i][j], ah[i], bh0, bh1);
                    MMA_BF16(acc[i][j], ah[i], bl0, bl1);
                    MMA_BF16(acc[i][j], al[i], bh0, bh1);
                }
            }
        }
        __syncthreads();
    }

    // ---- stage 2: relu(acc + b1) @ W2-slice, two 64-col halves ----
    const int c    = tid & 31;
    const int rgrp = tid >> 5;
    float sum[16];
#pragma unroll
    for (int rr = 0; rr < 16; rr++) sum[rr] = 0.0f;

#pragma unroll
    for (int h = 0; h < 2; h++) {
        __syncthreads();
        if (wn == h) {
#pragma unroll
            for (int i = 0; i < 2; i++)
#pragma unroll
                for (int j = 0; j < 8; j++) {
                    int row = wm * 32 + i * 16 + g;
                    int col = j * 8 + t * 2;
                    float bias0 = b1[bcol + h * 64 + col];
                    float bias1 = b1[bcol + h * 64 + col + 1];
                    float2 v0, v1;
                    v0.x = fmaxf(acc[i][j][0] + bias0, 0.0f);
                    v0.y = fmaxf(acc[i][j][1] + bias1, 0.0f);
                    v1.x = fmaxf(acc[i][j][2] + bias0, 0.0f);
                    v1.y = fmaxf(acc[i][j][3] + bias1, 0.0f);
                    *(float2*)&u.s2.Cs[row * CPITCH + col]       = v0;
                    *(float2*)&u.s2.Cs[(row + 8) * CPITCH + col] = v1;
                }
        }
#pragma unroll
        for (int l = 0; l < 8; l++) {
            int q = tid + l * 256;
            u.s2.W2s[q] = W2[(size_t)(bcol + h * 64 + (q >> 5)) * OUT_CH + (q & 31)];
        }
        __syncthreads();

#pragma unroll
        for (int k4 = 0; k4 < 16; k4++) {
            float w0 = u.s2.W2s[(k4 * 4 + 0) * 32 + c];
            float w1 = u.s2.W2s[(k4 * 4 + 1) * 32 + c];
            float w2 = u.s2.W2s[(k4 * 4 + 2) * 32 + c];
            float w3 = u.s2.W2s[(k4 * 4 + 3) * 32 + c];
#pragma unroll
            for (int rr = 0; rr < 16; rr++) {
                float4 cv = *(const float4*)&u.s2.Cs[(rgrp * 16 + rr) * CPITCH + k4 * 4];
                sum[rr] += cv.x * w0 + cv.y * w1 + cv.z * w2 + cv.w * w3;
            }
        }
    }

#pragma unroll
    for (int rr = 0; rr < 16; rr++) {
        int grow = brow + rgrp * 16 + rr;
        if (grow < N_NODES)
            atomicAdd(&g_h0[(size_t)grow * OUT_CH + c], sum[rr]);
    }
}

// ---------------- APPNP propagation: fused pull + combine ----------------
template <int SEL>
__device__ __forceinline__ const float* buf_const() {
    return SEL == 0 ? g_h0 : (SEL == 1 ? g_ha : g_hb);
}

// 8 lanes per node; lane q handles channels [4q, 4q+4).
// h_next = alpha*h0 + (1-alpha)*(sum_e coef*h[src] + selfc*h_cur)
template <int CUR, int NXT>
__global__ void pull_kernel(float* __restrict__ out) {
    const float* __restrict__ h = buf_const<CUR>();
    float* __restrict__ h_next =
        (NXT == 3) ? out : (NXT == 1 ? g_ha : g_hb);
    int t = blockIdx.x * blockDim.x + threadIdx.x;
    int node = t >> 3;
    int q = t & 7;
    if (node >= N_NODES) return;

    int beg = g_rowptr[node];
    int end = g_rowptr[node + 1];

    float4 acc = make_float4(0.f, 0.f, 0.f, 0.f);
    for (int i = beg; i < end; i++) {
        int2 ed = __ldg(&g_csr[i]);
        float cf = __int_as_float(ed.y);
        float4 hv = *(const float4*)&h[(size_t)ed.x * OUT_CH + q * 4];
        acc.x += cf * hv.x;
        acc.y += cf * hv.y;
        acc.z += cf * hv.z;
        acc.w += cf * hv.w;
    }

    size_t i4 = (size_t)node * 8 + q;
    float sc = g_selfc[node];
    float4 hc = ((const float4*)h)[i4];
    float4 h0v = ((const float4*)g_h0)[i4];
    float4 r;
    r.x = ALPHA * h0v.x + (1.0f - ALPHA) * (acc.x + sc * hc.x);
    r.y = ALPHA * h0v.y + (1.0f - ALPHA) * (acc.y + sc * hc.y);
    r.z = ALPHA * h0v.z + (1.0f - ALPHA) * (acc.z + sc * hc.z);
    r.w = ALPHA * h0v.w + (1.0f - ALPHA) * (acc.w + sc * hc.w);
    ((float4*)h_next)[i4] = r;
}

// ---------------- host launch ----------------
extern "C" void kernel_launch(void* const* d_in, const int* in_sizes, int n_in,
                              void* d_out, int out_size) {
    const float* x = nullptr;  const void* ei = nullptr;
    const float* W1 = nullptr; const float* b1 = nullptr;
    const float* W2 = nullptr; const float* b2 = nullptr;
    for (int i = 0; i < n_in; i++) {
        switch (in_sizes[i]) {
            case N_NODES * IN_CH:   x  = (const float*)d_in[i]; break;
            case 2 * N_EDGES:       ei = d_in[i]; break;
            case IN_CH * HID_CH:    W1 = (const float*)d_in[i]; break;
            case HID_CH:            b1 = (const float*)d_in[i]; break;
            case HID_CH * OUT_CH:   W2 = (const float*)d_in[i]; break;
            case OUT_CH:            b2 = (const float*)d_in[i]; break;
            default: break;
        }
    }
    float* out = (float*)d_out;

    const int NC4 = N_NODES * OUT_CH / 4;
    const int SCAN_NB = (N_NODES + SCAN_BLK - 1) / SCAN_BLK;  // 196

    detect_dtype_kernel<<<1, 32>>>((const int*)ei);
    init_deg_kernel<<<(N_NODES + 255) / 256, 256>>>();
    deg_edges_kernel<<<(N_EDGES + 255) / 256, 256>>>(ei);
    selfc_kernel<<<(N_NODES + 255) / 256, 256>>>();
    precompute_edges_kernel<<<(N_EDGES + 255) / 256, 256>>>(ei);

    // CSR build
    scanA_kernel<<<SCAN_NB, SCAN_BLK>>>();
    scanB_kernel<<<1, 256>>>(SCAN_NB);
    scanC_kernel<<<(N_NODES + 255) / 256, 256>>>();
    csr_fill_kernel<<<(N_EDGES + 255) / 256, 256>>>();

    // split-precision operand prep
    split_x_kernel<<<(N_NODES * IN_CH / 4 + 255) / 256, 256>>>(x);
    split_w1t_kernel<<<(HID_CH * IN_CH + 255) / 256, 256>>>(W1);

    // fused MLP: h0 = relu(x@W1+b1)@W2 + b2   (tensor cores, split-bf16)
    init_h0_bias_kernel<<<(NC4 + 255) / 256, 256>>>(b2);
    {
        dim3 grid((N_NODES + 127) / 128, HID_CH / 128);
        mlp_mma_kernel<<<grid, 256>>>(b1, W2);
    }

    // propagation: 10 fused pull+combine steps
    const int PB = (int)(((size_t)N_NODES * 8 + 255) / 256);  // 3125

    pull_kernel<0, 1><<<PB, 256>>>(out); // k=0
    pull_kernel<1, 2><<<PB, 256>>>(out); // k=1
    pull_kernel<2, 1><<<PB, 256>>>(out); // k=2
    pull_kernel<1, 2><<<PB, 256>>>(out); // k=3
    pull_kernel<2, 1><<<PB, 256>>>(out); // k=4
    pull_kernel<1, 2><<<PB, 256>>>(out); // k=5
    pull_kernel<2, 1><<<PB, 256>>>(out); // k=6
    pull_kernel<1, 2><<<PB, 256>>>(out); // k=7
    pull_kernel<2, 1><<<PB, 256>>>(out); // k=8
    pull_kernel<1, 3><<<PB, 256>>>(out); // k=9 -> out
}

// round 8
// speedup vs baseline: 3.7431x; 1.1073x over previous
#include <cuda_runtime.h>
#include <cuda_bf16.h>
#include <cstdint>

// ---------------- problem constants ----------------
#define N_NODES 100000
#define IN_CH   512
#define HID_CH  256
#define OUT_CH  32
#define N_EDGES 1600000
#define K_STEPS 10
#define ALPHA   0.1f

// ---------------- device scratch (no allocations allowed) ----------------
__device__ float g_h0[(size_t)N_NODES * OUT_CH];
__device__ float g_ha[(size_t)N_NODES * OUT_CH];
__device__ float g_hb[(size_t)N_NODES * OUT_CH];
__device__ int   g_deg[N_NODES];
__device__ float g_selfc[N_NODES];
__device__ int4  g_edges[N_EDGES];     // {src, dst, coef_bits, 0}
__device__ int   g_idx64;

// CSR (dst-sorted) for pull aggregation
__device__ int   g_rowptr[N_NODES + 1];
__device__ int   g_fill[N_NODES];
__device__ int   g_partial[256];
__device__ int2  g_csr[N_EDGES];       // {src, coef_bits}

// split-bf16 W1^T for the tensor-core GEMM ([n][k])
__device__ __align__(16) __nv_bfloat16 g_w1t_h[(size_t)HID_CH * IN_CH];
__device__ __align__(16) __nv_bfloat16 g_w1t_l[(size_t)HID_CH * IN_CH];

// ---------------- dtype detection ----------------
__global__ void detect_dtype_kernel(const int* __restrict__ ei32) {
    int t = threadIdx.x;
    int any = 0;
    for (int i = t; i < 1024; i += 32) any |= ei32[2 * i + 1];
#pragma unroll
    for (int o = 16; o; o >>= 1) any |= __shfl_xor_sync(0xffffffffu, any, o);
    if (t == 0) g_idx64 = (any == 0) ? 1 : 0;
}

__device__ __forceinline__ int load_idx(const void* ei, size_t pos, int is64) {
    long long v = is64 ? ((const long long*)ei)[pos] : (long long)((const int*)ei)[pos];
    if (v < 0) v = 0;
    if (v >= N_NODES) v = N_NODES - 1;
    return (int)v;
}

// ---------------- degree + edge precompute ----------------
__global__ void init_deg_kernel() {
    int i = blockIdx.x * blockDim.x + threadIdx.x;
    if (i < N_NODES) g_deg[i] = 1;
}

__global__ void deg_edges_kernel(const void* __restrict__ ei) {
    int e = blockIdx.x * blockDim.x + threadIdx.x;
    if (e >= N_EDGES) return;
    int is64 = g_idx64;
    atomicAdd(&g_deg[load_idx(ei, (size_t)N_EDGES + e, is64)], 1);
}

__global__ void precompute_edges_kernel(const void* __restrict__ ei) {
    int e = blockIdx.x * blockDim.x + threadIdx.x;
    if (e >= N_EDGES) return;
    int is64 = g_idx64;
    int s = load_idx(ei, e, is64);
    int d = load_idx(ei, (size_t)N_EDGES + e, is64);
    float c = rsqrtf((float)g_deg[s]) * rsqrtf((float)g_deg[d]);
    g_edges[e] = make_int4(s, d, __float_as_int(c), 0);
}

// ---------------- CSR build: 3-kernel exclusive scan + slot fill ----------------
#define SCAN_BLK 512
__global__ void scanA_kernel() {   // per-block exclusive scan of (deg-1), + selfc
    __shared__ int s[SCAN_BLK];
    int t = threadIdx.x;
    int i = blockIdx.x * SCAN_BLK + t;
    int v = (i < N_NODES) ? (g_deg[i] - 1) : 0;
    if (i < N_NODES) g_selfc[i] = 1.0f / (float)(v + 1);
    s[t] = v;
    __syncthreads();
#pragma unroll
    for (int off = 1; off < SCAN_BLK; off <<= 1) {
        int x = (t >= off) ? s[t - off] : 0;
        __syncthreads();
        s[t] += x;
        __syncthreads();
    }
    if (i < N_NODES) g_rowptr[i] = s[t] - v;   // exclusive within block
    if (t == SCAN_BLK - 1) g_partial[blockIdx.x] = s[t];
}

__global__ void scanB_kernel(int nblocks) {    // single block scans partials
    __shared__ int s[256];
    int t = threadIdx.x;
    int v = (t < nblocks) ? g_partial[t] : 0;
    s[t] = v;
    __syncthreads();
#pragma unroll
    for (int off = 1; off < 256; off <<= 1) {
        int x = (t >= off) ? s[t - off] : 0;
        __syncthreads();
        s[t] += x;
        __syncthreads();
    }
    if (t < nblocks) g_partial[t] = s[t] - v;  // exclusive
}

__global__ void scanC_kernel() {               // add block offsets, zero fill
    int i = blockIdx.x * blockDim.x + threadIdx.x;
    if (i < N_NODES) {
        g_rowptr[i] += g_partial[i / SCAN_BLK];
        g_fill[i] = 0;
    }
    if (i == 0) g_rowptr[N_NODES] = N_EDGES;
}

__global__ void csr_fill_kernel() {
    int e = blockIdx.x * blockDim.x + threadIdx.x;
    if (e >= N_EDGES) return;
    int4 ed = g_edges[e];
    int pos = g_rowptr[ed.y] + atomicAdd(&g_fill[ed.y], 1);
    g_csr[pos] = make_int2(ed.x, ed.z);
}

__global__ void init_h0_bias_kernel(const float* __restrict__ b2) {
    int i = blockIdx.x * blockDim.x + threadIdx.x;
    if (i < N_NODES * OUT_CH / 4) {
        const float4* b2v = (const float4*)b2;
        ((float4*)g_h0)[i] = b2v[i & 7];
    }
}

// ---------------- split-precision conversion ----------------
__device__ __forceinline__ void split1(float v, unsigned short& h, unsigned short& l) {
    __nv_bfloat16 hb = __float2bfloat16(v);
    float r = v - __bfloat162float(hb);
    __nv_bfloat16 lb = __float2bfloat16(r);
    h = *(unsigned short*)&hb;
    l = *(unsigned short*)&lb;
}

__global__ void split_w1t_kernel(const float* __restrict__ W1) {
    int i = blockIdx.x * blockDim.x + threadIdx.x;
    if (i >= HID_CH * IN_CH) return;
    int n = i >> 9;
    int k = i & 511;
    unsigned short h, l;
    split1(W1[(size_t)k * HID_CH + n], h, l);
    ((unsigned short*)g_w1t_h)[i] = h;
    ((unsigned short*)g_w1t_l)[i] = l;
}

// ---------------- tensor-core fused MLP ----------------
#define MMA_BF16(d, a, b0v, b1v)                                             \
    asm volatile(                                                            \
        "mma.sync.aligned.m16n8k16.row.col.f32.bf16.bf16.f32 "               \
        "{%0,%1,%2,%3}, {%4,%5,%6,%7}, {%8,%9}, {%0,%1,%2,%3};"              \
        : "+f"(d[0]), "+f"(d[1]), "+f"(d[2]), "+f"(d[3])                     \
        : "r"(a[0]), "r"(a[1]), "r"(a[2]), "r"(a[3]), "r"(b0v), "r"(b1v))

#define APITCH 40
#define CPITCH 68

__global__ __launch_bounds__(256)
void mlp_mma_kernel(const float* __restrict__ x,
                    const float* __restrict__ b1, const float* __restrict__ W2) {
    __shared__ __align__(16) union {
        struct {
            __nv_bfloat16 Ah[128 * APITCH], Al[128 * APITCH];
            __nv_bfloat16 Bh[128 * APITCH], Bl[128 * APITCH];
        } s1;
        struct { float Cs[128 * CPITCH]; float W2s[64 * 32]; } s2;
    } u;

    const int tid  = threadIdx.x;
    const int warp = tid >> 5;
    const int lane = tid & 31;
    const int wm = warp >> 1;
    const int wn = warp & 1;
    const int g  = lane >> 2;
    const int t  = lane & 3;
    const int brow = blockIdx.x * 128;
    const int bcol = blockIdx.y * 128;

    // A-tile mapping: 128 rows x 32 k fp32 = 1024 float4; 4 per thread
    const int arow = tid >> 1;              // per l: rows arow + l*... see below
    // use idx = tid + l*256 -> row = idx>>3 (0..127), seg = idx&7 (float4 col)
    // B-tile mapping: idx = tid + l*256 -> row = idx>>2, seg = idx&3 (uint4 of 8 bf16)
    (void)arow;

    float acc[2][8][4];
#pragma unroll
    for (int i = 0; i < 2; i++)
#pragma unroll
        for (int j = 0; j < 8; j++)
#pragma unroll
            for (int r = 0; r < 4; r++) acc[i][j][r] = 0.0f;

    float4 pa[4];
    uint4  pbh[2], pbl[2];

    auto load_tile = [&](int k0) {
#pragma unroll
        for (int l = 0; l < 4; l++) {
            int idx = tid + l * 256;
            int row = idx >> 3;
            int seg = idx & 7;
            if (brow + row < N_NODES)
                pa[l] = *(const float4*)&x[(size_t)(brow + row) * IN_CH + k0 + seg * 4];
            else
                pa[l] = make_float4(0.f, 0.f, 0.f, 0.f);
        }
#pragma unroll
        for (int l = 0; l < 2; l++) {
            int idx = tid + l * 256;
            int row = idx >> 2;
            int seg = idx & 3;
            size_t go = (size_t)(bcol + row) * IN_CH + k0 + seg * 8;
            pbh[l] = *(const uint4*)&g_w1t_h[go];
            pbl[l] = *(const uint4*)&g_w1t_l[go];
        }
    };

    auto store_tile = [&]() {
#pragma unroll
        for (int l = 0; l < 4; l++) {
            int idx = tid + l * 256;
            int row = idx >> 3;
            int seg = idx & 7;
            ushort4 hh, ll;
            split1(pa[l].x, hh.x, ll.x);
            split1(pa[l].y, hh.y, ll.y);
            split1(pa[l].z, hh.z, ll.z);
            split1(pa[l].w, hh.w, ll.w);
            *(ushort4*)&u.s1.Ah[row * APITCH + seg * 4] = hh;
            *(ushort4*)&u.s1.Al[row * APITCH + seg * 4] = ll;
        }
#pragma unroll
        for (int l = 0; l < 2; l++) {
            int idx = tid + l * 256;
            int row = idx >> 2;
            int seg = idx & 3;
            *(uint4*)&u.s1.Bh[row * APITCH + seg * 8] = pbh[l];
            *(uint4*)&u.s1.Bl[row * APITCH + seg * 8] = pbl[l];
        }
    };

    load_tile(0);
    store_tile();
    __syncthreads();

    for (int k0 = 0; k0 < IN_CH; k0 += 32) {
        const bool more = (k0 + 32) < IN_CH;
        if (more) load_tile(k0 + 32);   // overlap with MMAs below

#pragma unroll
        for (int kk = 0; kk < 32; kk += 16) {
            uint32_t ah[2][4], al[2][4];
#pragma unroll
            for (int i = 0; i < 2; i++) {
                int r = wm * 32 + i * 16 + g;
                int base = r * APITCH + kk + t * 2;
                ah[i][0] = *(const uint32_t*)&u.s1.Ah[base];
                ah[i][1] = *(const uint32_t*)&u.s1.Ah[base + 8 * APITCH];
                ah[i][2] = *(const uint32_t*)&u.s1.Ah[base + 8];
                ah[i][3] = *(const uint32_t*)&u.s1.Ah[base + 8 * APITCH + 8];
                al[i][0] = *(const uint32_t*)&u.s1.Al[base];
                al[i][1] = *(const uint32_t*)&u.s1.Al[base + 8 * APITCH];
                al[i][2] = *(const uint32_t*)&u.s1.Al[base + 8];
                al[i][3] = *(const uint32_t*)&u.s1.Al[base + 8 * APITCH + 8];
            }
#pragma unroll
            for (int j = 0; j < 8; j++) {
                int n = wn * 64 + j * 8 + g;
                int bb = n * APITCH + kk + t * 2;
                uint32_t bh0 = *(const uint32_t*)&u.s1.Bh[bb];
                uint32_t bh1 = *(const uint32_t*)&u.s1.Bh[bb + 8];
                uint32_t bl0 = *(const uint32_t*)&u.s1.Bl[bb];
                uint32_t bl1 = *(const uint32_t*)&u.s1.Bl[bb + 8];
#pragma unroll
                for (int i = 0; i < 2; i++) {
                    MMA_BF16(acc[i][j], ah[i], bh0, bh1);
                    MMA_BF16(acc[i][j], ah[i], bl0, bl1);
                    MMA_BF16(acc[i][j], al[i], bh0, bh1);
                }
            }
        }
        __syncthreads();
        if (more) {
            store_tile();
            __syncthreads();
        }
    }

    // ---- stage 2: relu(acc + b1) @ W2-slice, two 64-col halves ----
    const int c    = tid & 31;
    const int rgrp = tid >> 5;
    float sum[16];
#pragma unroll
    for (int rr = 0; rr < 16; rr++) sum[rr] = 0.0f;

#pragma unroll
    for (int h = 0; h < 2; h++) {
        __syncthreads();
        if (wn == h) {
#pragma unroll
            for (int i = 0; i < 2; i++)
#pragma unroll
                for (int j = 0; j < 8; j++) {
                    int row = wm * 32 + i * 16 + g;
                    int col = j * 8 + t * 2;
                    float bias0 = b1[bcol + h * 64 + col];
                    float bias1 = b1[bcol + h * 64 + col + 1];
                    float2 v0, v1;
                    v0.x = fmaxf(acc[i][j][0] + bias0, 0.0f);
                    v0.y = fmaxf(acc[i][j][1] + bias1, 0.0f);
                    v1.x = fmaxf(acc[i][j][2] + bias0, 0.0f);
                    v1.y = fmaxf(acc[i][j][3] + bias1, 0.0f);
                    *(float2*)&u.s2.Cs[row * CPITCH + col]       = v0;
                    *(float2*)&u.s2.Cs[(row + 8) * CPITCH + col] = v1;
                }
        }
#pragma unroll
        for (int l = 0; l < 8; l++) {
            int q = tid + l * 256;
            u.s2.W2s[q] = W2[(size_t)(bcol + h * 64 + (q >> 5)) * OUT_CH + (q & 31)];
        }
        __syncthreads();

#pragma unroll
        for (int k4 = 0; k4 < 16; k4++) {
            float w0 = u.s2.W2s[(k4 * 4 + 0) * 32 + c];
            float w1 = u.s2.W2s[(k4 * 4 + 1) * 32 + c];
            float w2 = u.s2.W2s[(k4 * 4 + 2) * 32 + c];
            float w3 = u.s2.W2s[(k4 * 4 + 3) * 32 + c];
#pragma unroll
            for (int rr = 0; rr < 16; rr++) {
                float4 cv = *(const float4*)&u.s2.Cs[(rgrp * 16 + rr) * CPITCH + k4 * 4];
                sum[rr] += cv.x * w0 + cv.y * w1 + cv.z * w2 + cv.w * w3;
            }
        }
    }

#pragma unroll
    for (int rr = 0; rr < 16; rr++) {
        int grow = brow + rgrp * 16 + rr;
        if (grow < N_NODES)
            atomicAdd(&g_h0[(size_t)grow * OUT_CH + c], sum[rr]);
    }
}

// ---------------- APPNP propagation: fused pull + combine ----------------
template <int SEL>
__device__ __forceinline__ const float* buf_const() {
    return SEL == 0 ? g_h0 : (SEL == 1 ? g_ha : g_hb);
}

// 8 lanes per node; lane q handles channels [4q, 4q+4).
template <int CUR, int NXT>
__global__ void pull_kernel(float* __restrict__ out) {
    const float* __restrict__ h = buf_const<CUR>();
    float* __restrict__ h_next =
        (NXT == 3) ? out : (NXT == 1 ? g_ha : g_hb);
    int t = blockIdx.x * blockDim.x + threadIdx.x;
    int node = t >> 3;
    int q = t & 7;
    if (node >= N_NODES) return;

    int beg = g_rowptr[node];
    int end = g_rowptr[node + 1];

    float4 acc = make_float4(0.f, 0.f, 0.f, 0.f);
#pragma unroll 2
    for (int i = beg; i < end; i++) {
        int2 ed = __ldg(&g_csr[i]);
        float cf = __int_as_float(ed.y);
        float4 hv = *(const float4*)&h[(size_t)ed.x * OUT_CH + q * 4];
        acc.x += cf * hv.x;
        acc.y += cf * hv.y;
        acc.z += cf * hv.z;
        acc.w += cf * hv.w;
    }

    size_t i4 = (size_t)node * 8 + q;
    float sc = g_selfc[node];
    float4 hc = ((const float4*)h)[i4];
    float4 h0v = ((const float4*)g_h0)[i4];
    float4 r;
    r.x = ALPHA * h0v.x + (1.0f - ALPHA) * (acc.x + sc * hc.x);
    r.y = ALPHA * h0v.y + (1.0f - ALPHA) * (acc.y + sc * hc.y);
    r.z = ALPHA * h0v.z + (1.0f - ALPHA) * (acc.z + sc * hc.z);
    r.w = ALPHA * h0v.w + (1.0f - ALPHA) * (acc.w + sc * hc.w);
    ((float4*)h_next)[i4] = r;
}

// ---------------- host launch ----------------
extern "C" void kernel_launch(void* const* d_in, const int* in_sizes, int n_in,
                              void* d_out, int out_size) {
    const float* x = nullptr;  const void* ei = nullptr;
    const float* W1 = nullptr; const float* b1 = nullptr;
    const float* W2 = nullptr; const float* b2 = nullptr;
    for (int i = 0; i < n_in; i++) {
        switch (in_sizes[i]) {
            case N_NODES * IN_CH:   x  = (const float*)d_in[i]; break;
            case 2 * N_EDGES:       ei = d_in[i]; break;
            case IN_CH * HID_CH:    W1 = (const float*)d_in[i]; break;
            case HID_CH:            b1 = (const float*)d_in[i]; break;
            case HID_CH * OUT_CH:   W2 = (const float*)d_in[i]; break;
            case OUT_CH:            b2 = (const float*)d_in[i]; break;
            default: break;
        }
    }
    float* out = (float*)d_out;

    const int NC4 = N_NODES * OUT_CH / 4;
    const int SCAN_NB = (N_NODES + SCAN_BLK - 1) / SCAN_BLK;  // 196

    detect_dtype_kernel<<<1, 32>>>((const int*)ei);
    init_deg_kernel<<<(N_NODES + 255) / 256, 256>>>();
    deg_edges_kernel<<<(N_EDGES + 255) / 256, 256>>>(ei);
    precompute_edges_kernel<<<(N_EDGES + 255) / 256, 256>>>(ei);

    // CSR build (selfc fused into scanA)
    scanA_kernel<<<SCAN_NB, SCAN_BLK>>>();
    scanB_kernel<<<1, 256>>>(SCAN_NB);
    scanC_kernel<<<(N_NODES + 255) / 256, 256>>>();
    csr_fill_kernel<<<(N_EDGES + 255) / 256, 256>>>();

    // W1 split (x is split in-kernel)
    split_w1t_kernel<<<(HID_CH * IN_CH + 255) / 256, 256>>>(W1);

    // fused MLP: h0 = relu(x@W1+b1)@W2 + b2   (tensor cores, split-bf16)
    init_h0_bias_kernel<<<(NC4 + 255) / 256, 256>>>(b2);
    {
        dim3 grid((N_NODES + 127) / 128, HID_CH / 128);
        mlp_mma_kernel<<<grid, 256>>>(x, b1, W2);
    }

    // propagation: 10 fused pull+combine steps
    const int PB = (int)(((size_t)N_NODES * 8 + 255) / 256);  // 3125

    pull_kernel<0, 1><<<PB, 256>>>(out); // k=0
    pull_kernel<1, 2><<<PB, 256>>>(out); // k=1
    pull_kernel<2, 1><<<PB, 256>>>(out); // k=2
    pull_kernel<1, 2><<<PB, 256>>>(out); // k=3
    pull_kernel<2, 1><<<PB, 256>>>(out); // k=4
    pull_kernel<1, 2><<<PB, 256>>>(out); // k=5
    pull_kernel<2, 1><<<PB, 256>>>(out); // k=6
    pull_kernel<1, 2><<<PB, 256>>>(out); // k=7
    pull_kernel<2, 1><<<PB, 256>>>(out); // k=8
    pull_kernel<1, 3><<<PB, 256>>>(out); // k=9 -> out
}